// round 2
// baseline (speedup 1.0000x reference)
#include <cuda_runtime.h>

// ---------------------------------------------------------------------------
// DIN forward, fused.
//   Identities used (vs. the reference):
//     kh  = hist @ (Wi@Wk) + bi@Wk          (never materialize hist@Wi)
//     qh  = cand @ (Wi@Wq) + bi@Wq
//     interest = (attn @ hist) @ Wi + bi    (softmax weights sum to 1)
//     avg      = (mask-mean of hist) @ Wi + bi
//     BatchNorm folds into MLP weights/biases.
//   prep (tiny) -> din_main (1 CTA / batch row, online softmax, one streaming
//   pass over history) -> din_mlp (folded 192->128->64->32->1 + sigmoid).
// ---------------------------------------------------------------------------

#define EPSBN 1e-5f

// ---- device scratch (no allocations allowed) ----
__device__ float d_WikT[64 * 128];     // [a][f]  = (Wi@Wk)^T
__device__ float d_Wiq[128 * 64];      // [f][a]  = Wi@Wq
__device__ float d_bqk[64];            // bi@Wq + bi@Wk
__device__ float d_W1f[192 * 128];     // BN-folded MLP weights, [in][out]
__device__ float d_b1f[128];
__device__ float d_W2f[128 * 64];
__device__ float d_b2f[64];
__device__ float d_W3f[64 * 32];
__device__ float d_b3f[32];
__device__ float d_Xbuf[8192 * 192];   // MLP input [B, 3E] = [interest|cand|avg]

// ---------------------------------------------------------------------------
// prep: fold weights. ~2 MFLOP, negligible.
// ---------------------------------------------------------------------------
__global__ __launch_bounds__(256) void prep_kernel(
    const float* __restrict__ Wi, const float* __restrict__ bi,
    const float* __restrict__ Wq, const float* __restrict__ Wk,
    const float* __restrict__ W1, const float* __restrict__ b1,
    const float* __restrict__ g1, const float* __restrict__ be1,
    const float* __restrict__ m1, const float* __restrict__ v1,
    const float* __restrict__ W2, const float* __restrict__ b2,
    const float* __restrict__ g2, const float* __restrict__ be2,
    const float* __restrict__ m2, const float* __restrict__ v2,
    const float* __restrict__ W3, const float* __restrict__ b3,
    const float* __restrict__ g3, const float* __restrict__ be3,
    const float* __restrict__ m3, const float* __restrict__ v3)
{
    const int t0 = blockIdx.x * blockDim.x + threadIdx.x;
    const int stride = gridDim.x * blockDim.x;

    // Wik^T and Wiq
    for (int idx = t0; idx < 64 * 128; idx += stride) {
        const int a = idx >> 7, f = idx & 127;
        float sk = 0.f, sq = 0.f;
        for (int e = 0; e < 64; e++) {
            const float wie = Wi[f * 64 + e];
            sk = fmaf(wie, Wk[e * 64 + a], sk);
            sq = fmaf(wie, Wq[e * 64 + a], sq);
        }
        d_WikT[a * 128 + f] = sk;
        d_Wiq[f * 64 + a]   = sq;
    }
    // combined attention bias
    for (int a = t0; a < 64; a += stride) {
        float s = 0.f;
        for (int e = 0; e < 64; e++)
            s = fmaf(bi[e], Wk[e * 64 + a] + Wq[e * 64 + a], s);
        d_bqk[a] = s;
    }
    // BN-folded MLP layer 1
    for (int idx = t0; idx < 192 * 128; idx += stride) {
        const int h = idx & 127;
        d_W1f[idx] = W1[idx] * (g1[h] * rsqrtf(v1[h] + EPSBN));
    }
    for (int h = t0; h < 128; h += stride) {
        const float sc = g1[h] * rsqrtf(v1[h] + EPSBN);
        d_b1f[h] = (b1[h] - m1[h]) * sc + be1[h];
    }
    // layer 2
    for (int idx = t0; idx < 128 * 64; idx += stride) {
        const int h = idx & 63;
        d_W2f[idx] = W2[idx] * (g2[h] * rsqrtf(v2[h] + EPSBN));
    }
    for (int h = t0; h < 64; h += stride) {
        const float sc = g2[h] * rsqrtf(v2[h] + EPSBN);
        d_b2f[h] = (b2[h] - m2[h]) * sc + be2[h];
    }
    // layer 3
    for (int idx = t0; idx < 64 * 32; idx += stride) {
        const int h = idx & 31;
        d_W3f[idx] = W3[idx] * (g3[h] * rsqrtf(v3[h] + EPSBN));
    }
    for (int h = t0; h < 32; h += stride) {
        const float sc = g3[h] * rsqrtf(v3[h] + EPSBN);
        d_b3f[h] = (b3[h] - m3[h]) * sc + be3[h];
    }
}

// ---------------------------------------------------------------------------
// din_main: one CTA (256 threads = 8 warps) per batch row b.
//   Single streaming pass over history[b] (200x128) with online softmax.
//   Per warp: 3 rows per chunk; per lane: 2 attention columns (a, a+32).
// Static shared (floats):
//   sWik [64][132] padded  = 8448   (conflict-free LDS.128: 132%32=4 ->
//                                    8 lanes/phase hit distinct banks)
//   srow [8w][3r][128]     = 3072   (also reused post-loop as merge buffers)
//   scand 128, sqrel 64
//   Total = 11712 floats = 46848 B  (<48KB: no cudaFuncSetAttribute needed)
// ---------------------------------------------------------------------------
__global__ __launch_bounds__(256) void din_main(
    const float* __restrict__ cand,
    const float* __restrict__ hist,
    const int*   __restrict__ hlen,
    const float* __restrict__ bi,
    const float* __restrict__ Wv,
    const float* __restrict__ Wi)
{
    __shared__ float sWik[64 * 132];
    __shared__ float srow[3072];
    __shared__ float scand[128];
    __shared__ float sqrel[64];

    // post-loop overlays onto srow (guarded by __syncthreads after the loop)
    float* satt = srow;            // [8][128]
    float* savg = srow + 1024;     // [8][128]
    float* smx  = srow + 2048;     // [8]
    float* slx  = srow + 2056;     // [8]
    float* spa  = srow + 2064;     // [128]
    float* spv  = srow + 2192;     // [128]

    const int b    = blockIdx.x;
    const int tid  = threadIdx.x;
    const int w    = tid >> 5;
    const int lane = tid & 31;
    const int len  = hlen[b];

    // stage Wik^T into padded smem (coalesced float4) + cand
    {
        const float4* wik4 = (const float4*)d_WikT;
        for (int i = tid; i < 64 * 32; i += 256) {
            const float4 v = wik4[i];
            const int a = i >> 5, f = (i & 31) << 2;
            *(float4*)(sWik + a * 132 + f) = v;
        }
        if (tid < 32)
            ((float4*)scand)[tid] = ((const float4*)(cand + (long)b * 128))[tid];
    }
    __syncthreads();

    // qrel[a] = cand@Wiq + (bq+bk);  cand embedding -> Xbuf[64:128]
    if (tid < 64) {
        const int a = tid;
        float acc = d_bqk[a];
        #pragma unroll 8
        for (int f = 0; f < 128; f++) acc = fmaf(scand[f], d_Wiq[f * 64 + a], acc);
        sqrel[a] = acc;
    } else if (tid < 128) {
        const int e = tid - 64;
        float acc = bi[e];
        #pragma unroll 8
        for (int f = 0; f < 128; f++) acc = fmaf(scand[f], Wi[f * 64 + e], acc);
        d_Xbuf[(long)b * 192 + 64 + e] = acc;
    }
    __syncthreads();

    const int a0 = lane, a1 = lane + 32;
    const float q0 = sqrel[a0], q1 = sqrel[a1];
    const float v0 = Wv[a0],    v1 = Wv[a1];

    float  m = -1e30f, l = 0.f;
    float4 pa = make_float4(0.f, 0.f, 0.f, 0.f);   // attn-weighted pooled (f=lane*4..+3)
    float4 av = make_float4(0.f, 0.f, 0.f, 0.f);   // masked-sum pooled

    const float4* h4 = (const float4*)hist + (long)b * 200 * 32;
    float* myrow = srow + w * 3 * 128;
    const float* wk0 = sWik + a0 * 132;
    const float* wk1 = sWik + a1 * 132;

    // 9 chunks of 24 rows (8 warps x 3 rows); rows >= 200 are guarded.
    for (int c = 0; c < 9; c++) {
        const int base = c * 24 + w * 3;
        if (base >= 200) break;

        __syncwarp();
        #pragma unroll
        for (int r = 0; r < 3; r++)
            if (base + r < 200)
                *(float4*)(myrow + r * 128 + lane * 4) = h4[(base + r) * 32 + lane];
        __syncwarp();

        // kh[r][{a0,a1}] = row_r @ Wik
        float kk[3][2];
        #pragma unroll
        for (int r = 0; r < 3; r++) { kk[r][0] = 0.f; kk[r][1] = 0.f; }

        #pragma unroll 8
        for (int ff = 0; ff < 32; ff++) {
            const int f = ff << 2;
            const float4 wa = *(const float4*)(wk0 + f);
            const float4 wb = *(const float4*)(wk1 + f);
            #pragma unroll
            for (int r = 0; r < 3; r++) {
                const float4 x = *(const float4*)(myrow + r * 128 + f);
                kk[r][0] = fmaf(x.x, wa.x, kk[r][0]);
                kk[r][0] = fmaf(x.y, wa.y, kk[r][0]);
                kk[r][0] = fmaf(x.z, wa.z, kk[r][0]);
                kk[r][0] = fmaf(x.w, wa.w, kk[r][0]);
                kk[r][1] = fmaf(x.x, wb.x, kk[r][1]);
                kk[r][1] = fmaf(x.y, wb.y, kk[r][1]);
                kk[r][1] = fmaf(x.z, wb.z, kk[r][1]);
                kk[r][1] = fmaf(x.w, wb.w, kk[r][1]);
            }
        }

        // scores: sum_a relu(q+kh)*Wv  (butterfly reduce over the 64 a-cols)
        float sc[3];
        #pragma unroll
        for (int r = 0; r < 3; r++)
            sc[r] = v0 * fmaxf(q0 + kk[r][0], 0.f) + v1 * fmaxf(q1 + kk[r][1], 0.f);
        #pragma unroll
        for (int off = 16; off; off >>= 1) {
            #pragma unroll
            for (int r = 0; r < 3; r++)
                sc[r] += __shfl_xor_sync(0xffffffffu, sc[r], off);
        }

        // mask + online softmax update
        float cmax = -1e30f;
        #pragma unroll
        for (int r = 0; r < 3; r++) {
            sc[r] = (base + r < len) ? sc[r] : -1e30f;
            cmax = fmaxf(cmax, sc[r]);
        }
        const float mnew = fmaxf(m, cmax);
        const float corr = __expf(m - mnew);
        l *= corr;
        pa.x *= corr; pa.y *= corr; pa.z *= corr; pa.w *= corr;
        #pragma unroll
        for (int r = 0; r < 3; r++) {
            if (base + r < len) {
                const float p = __expf(sc[r] - mnew);
                l += p;
                const float4 x = *(const float4*)(myrow + r * 128 + lane * 4);
                pa.x = fmaf(p, x.x, pa.x);
                pa.y = fmaf(p, x.y, pa.y);
                pa.z = fmaf(p, x.z, pa.z);
                pa.w = fmaf(p, x.w, pa.w);
                av.x += x.x; av.y += x.y; av.z += x.z; av.w += x.w;
            }
        }
        m = mnew;
    }

    // All warps must be done with their staging rows before the overlay writes.
    __syncthreads();

    // merge 8 warps' online-softmax states (overlaid into srow)
    *(float4*)(satt + w * 128 + lane * 4) = pa;
    *(float4*)(savg + w * 128 + lane * 4) = av;
    if (lane == 0) { smx[w] = m; slx[w] = l; }
    __syncthreads();

    if (tid < 128) {
        float M = smx[0];
        #pragma unroll
        for (int i = 1; i < 8; i++) M = fmaxf(M, smx[i]);
        float T = 0.f, sa = 0.f, sv = 0.f;
        #pragma unroll
        for (int i = 0; i < 8; i++) {
            const float wfac = __expf(smx[i] - M);
            T += slx[i] * wfac;
            sa = fmaf(satt[i * 128 + tid], wfac, sa);
            sv += savg[i * 128 + tid];
        }
        spa[tid] = sa / T;
        spv[tid] = sv / (float)len;
    }
    __syncthreads();

    // E-project pooled vectors once: interest -> X[0:64], avg -> X[128:192]
    if (tid < 64) {
        const int e = tid;
        float ai = bi[e], aa = bi[e];
        #pragma unroll 8
        for (int f = 0; f < 128; f++) {
            const float wt = Wi[f * 64 + e];
            ai = fmaf(spa[f], wt, ai);
            aa = fmaf(spv[f], wt, aa);
        }
        d_Xbuf[(long)b * 192 + e]       = ai;
        d_Xbuf[(long)b * 192 + 128 + e] = aa;
    }
}

// ---------------------------------------------------------------------------
// din_mlp: folded 192->128->64->32->1 MLP + sigmoid. 32 rows per CTA.
// ---------------------------------------------------------------------------
__global__ __launch_bounds__(256) void din_mlp(
    const float* __restrict__ Wo, const float* __restrict__ bo,
    float* __restrict__ out)
{
    __shared__ float sb[6144 + 4096];        // 40 KB
    float* xt = sb;                          // [32][192]
    float* h1 = sb + 6144;                   // [32][128]
    const int blk = blockIdx.x;
    const int tid = threadIdx.x;

    const float* Xb = d_Xbuf + (long)blk * 32 * 192;
    for (int i = tid; i < 32 * 192; i += 256) xt[i] = Xb[i];
    __syncthreads();

    {   // layer 1: per thread 16 rows x 1 col
        const int h = tid & 127, rg = tid >> 7;
        float acc[16];
        const float bb = d_b1f[h];
        #pragma unroll
        for (int r = 0; r < 16; r++) acc[r] = bb;
        for (int i = 0; i < 192; i++) {
            const float wv = d_W1f[i * 128 + h];
            #pragma unroll
            for (int r = 0; r < 16; r++)
                acc[r] = fmaf(xt[(rg * 16 + r) * 192 + i], wv, acc[r]);
        }
        #pragma unroll
        for (int r = 0; r < 16; r++)
            h1[(rg * 16 + r) * 128 + h] = fmaxf(acc[r], 0.f);
    }
    __syncthreads();

    float* h2 = sb;                          // reuse xt region: [32][64]
    {   // layer 2
        const int a = tid & 63, rg = tid >> 6;
        float acc[8];
        const float bb = d_b2f[a];
        #pragma unroll
        for (int r = 0; r < 8; r++) acc[r] = bb;
        for (int i = 0; i < 128; i++) {
            const float wv = d_W2f[i * 64 + a];
            #pragma unroll
            for (int r = 0; r < 8; r++)
                acc[r] = fmaf(h1[(rg * 8 + r) * 128 + i], wv, acc[r]);
        }
        #pragma unroll
        for (int r = 0; r < 8; r++)
            h2[(rg * 8 + r) * 64 + a] = fmaxf(acc[r], 0.f);
    }
    __syncthreads();

    float* h3 = sb + 2048;                   // [32][32]
    {   // layer 3
        const int o = tid & 31, rg = tid >> 5;
        float acc[4];
        const float bb = d_b3f[o];
        #pragma unroll
        for (int r = 0; r < 4; r++) acc[r] = bb;
        for (int i = 0; i < 64; i++) {
            const float wv = d_W3f[i * 32 + o];
            #pragma unroll
            for (int r = 0; r < 4; r++)
                acc[r] = fmaf(h2[(rg * 4 + r) * 64 + i], wv, acc[r]);
        }
        #pragma unroll
        for (int r = 0; r < 4; r++)
            h3[(rg * 4 + r) * 32 + o] = fmaxf(acc[r], 0.f);
    }
    __syncthreads();

    if (tid < 32) {
        float acc = bo[0];
        #pragma unroll
        for (int j = 0; j < 32; j++) acc = fmaf(h3[tid * 32 + j], Wo[j], acc);
        out[blk * 32 + tid] = 1.f / (1.f + __expf(-acc));
    }
}

// ---------------------------------------------------------------------------
extern "C" void kernel_launch(void* const* d_in, const int* in_sizes, int n_in,
                              void* d_out, int out_size)
{
    const float* cand = (const float*)d_in[0];
    const float* hist = (const float*)d_in[1];
    const int*   hlen = (const int*)d_in[2];
    const float* Wi   = (const float*)d_in[3];
    const float* bi   = (const float*)d_in[4];
    const float* Wq   = (const float*)d_in[5];
    const float* Wk   = (const float*)d_in[6];
    const float* Wv   = (const float*)d_in[7];
    const float* W1   = (const float*)d_in[8];
    const float* b1   = (const float*)d_in[9];
    const float* g1   = (const float*)d_in[10];
    const float* be1  = (const float*)d_in[11];
    const float* m1   = (const float*)d_in[12];
    const float* v1   = (const float*)d_in[13];
    const float* W2   = (const float*)d_in[14];
    const float* b2   = (const float*)d_in[15];
    const float* g2   = (const float*)d_in[16];
    const float* be2  = (const float*)d_in[17];
    const float* m2   = (const float*)d_in[18];
    const float* v2   = (const float*)d_in[19];
    const float* W3   = (const float*)d_in[20];
    const float* b3   = (const float*)d_in[21];
    const float* g3   = (const float*)d_in[22];
    const float* be3  = (const float*)d_in[23];
    const float* m3   = (const float*)d_in[24];
    const float* v3   = (const float*)d_in[25];
    const float* Wo   = (const float*)d_in[26];
    const float* bo   = (const float*)d_in[27];
    float* out = (float*)d_out;

    prep_kernel<<<48, 256>>>(Wi, bi, Wq, Wk,
                             W1, b1, g1, be1, m1, v1,
                             W2, b2, g2, be2, m2, v2,
                             W3, b3, g3, be3, m3, v3);
    din_main<<<8192, 256>>>(cand, hist, hlen, bi, Wv, Wi);
    din_mlp<<<256, 256>>>(Wo, bo, out);
}